// round 16
// baseline (speedup 1.0000x reference)
#include <cuda_runtime.h>
#include <cuda_fp16.h>
#include <cstdint>
#include <math.h>

#define HIDDEN   1024
#define BATCH    512
#define FEAT     1024
#define TSTEPS   100
#define TIME_TOT 103
#define FOURH    4096
#define MTOT     (TSTEPS * BATCH)   // 51200

// per CTA: 2 stages x (A 32KB + B 16KB) = 96KB; 2 CTAs/SM = 192KB
#define STG_B    49152
#define SMEM_SZ  98304

// ------------------------------ scratch (device globals, no allocs) ----------
__device__ __align__(16) __half g_WRp[32 * 32 * 8192];           // [W;R] per-strip (16MB)
__device__ __align__(16) __half g_xp[((size_t)MTOT + 512) * 1024]; // padded 1 step
__device__ __align__(16) __half g_hp[2][BATCH * HIDDEN];         // permuted h ping-pong
__device__ __align__(16) __half g_zxh[(size_t)TSTEPS * 256 * 8192]; // zx fp16 (420MB)
__device__ unsigned g_sync4[4];      // h-publish counters, per by128 group (32 H each)
__device__ unsigned g_xdone[128];    // zx progress, per tile: value = t*2 + half + 1

// ------------------------------ asm helpers ----------------------------------
#define CP16(dst, src) \
    asm volatile("cp.async.cg.shared.global [%0], [%1], 16;" :: "r"(dst), "l"(src))
#define CP_COMMIT() asm volatile("cp.async.commit_group;" ::: "memory")
#define CP_WAIT1()  asm volatile("cp.async.wait_group 1;" ::: "memory")
#define CP_WAIT0()  asm volatile("cp.async.wait_group 0;" ::: "memory")

__device__ __forceinline__ uint4 lds128u(uint32_t a) {
    uint4 v;
    asm volatile("ld.shared.v4.b32 {%0,%1,%2,%3}, [%4];"
                 : "=r"(v.x), "=r"(v.y), "=r"(v.z), "=r"(v.w) : "r"(a));
    return v;
}
__device__ __forceinline__ uint2 lds64u(uint32_t a) {
    uint2 v;
    asm volatile("ld.shared.v2.b32 {%0,%1}, [%2];" : "=r"(v.x), "=r"(v.y) : "r"(a));
    return v;
}
__device__ __forceinline__ uint4 ldg_cg128(const char* p) {
    uint4 v;
    asm volatile("ld.global.cg.v4.u32 {%0,%1,%2,%3}, [%4];"
                 : "=r"(v.x), "=r"(v.y), "=r"(v.z), "=r"(v.w) : "l"(p));
    return v;
}
__device__ __forceinline__ void stg_cg128(char* p, uint4 v) {
    asm volatile("st.global.cg.v4.u32 [%0], {%1,%2,%3,%4};"
                 :: "l"(p), "r"(v.x), "r"(v.y), "r"(v.z), "r"(v.w) : "memory");
}
__device__ __forceinline__ void mma_f16(float c[4], uint4 a, uint2 b) {
    asm volatile(
        "mma.sync.aligned.m16n8k16.row.col.f32.f16.f16.f32 "
        "{%0,%1,%2,%3}, {%4,%5,%6,%7}, {%8,%9}, {%0,%1,%2,%3};"
        : "+f"(c[0]), "+f"(c[1]), "+f"(c[2]), "+f"(c[3])
        : "r"(a.x), "r"(a.y), "r"(a.z), "r"(a.w), "r"(b.x), "r"(b.y));
}
__device__ __forceinline__ float sigm_f(float z) {
    return __fdividef(1.f, 1.f + __expf(-z));
}
__device__ __forceinline__ float tanh_f(float z) {
    return 1.f - __fdividef(2.f, __expf(2.f * z) + 1.f);
}
__device__ __forceinline__ uint32_t packh2(float a, float b) {
    __half2 h = __floats2half2_rn(a, b);
    return *(uint32_t*)&h;
}

// ------------------------------ prep (single launch) --------------------------
#define N1 (32 * 32 * 4096)
#define N2 (MTOT * 1024 / 16)
#define N3 (BATCH * HIDDEN / 2)

__global__ void prep_all(const float* __restrict__ W, const float* __restrict__ R,
                         const float* __restrict__ x)
{
    int idx = blockIdx.x * blockDim.x + threadIdx.x;
    if (idx < N1) {
        int v   = idx & 3;
        int tig = (idx >> 2) & 3;
        int grp = (idx >> 4) & 7;
        int k16 = (idx >> 7) & 3;
        int mi  = (idx >> 9) & 3;
        int wm  = (idx >> 11) & 1;
        int kt  = (idx >> 12) & 31;
        int cb  = idx >> 17;
        int r8  = v & 1;
        int khi = (v >> 1) * 8;
        int q   = mi * 2 + r8;
        int gate = q & 3;
        int jhi  = q >> 2;
        int j = cb * 32 + wm * 16 + jhi * 8 + grp;
        int kl = k16 * 16 + khi + 2 * tig;
        const float* src = (kt < 16) ? W : R;
        int k = (kt < 16 ? kt : kt - 16) * 64 + kl;
        int col = gate * 1024 + j;
        ((__half2*)g_WRp)[idx] = __floats2half2_rn(src[(size_t)k * FOURH + col],
                                                   src[(size_t)(k + 1) * FOURH + col]);
    } else if (idx < N1 + N2) {
        int id = idx - N1;
        int grp = id & 7;
        int k16 = (id >> 3) & 3;
        int kt  = (id >> 5) & 15;
        int blk = id >> 9;
        int m = blk * 8 + grp;
        int t = m >> 9, bb = m & 511;
        const float* s = x + ((size_t)bb * TIME_TOT + t) * FEAT + kt * 64 + k16 * 16;
        float f[16];
#pragma unroll
        for (int qd = 0; qd < 4; qd++) *(float4*)(f + qd * 4) = *(const float4*)(s + qd * 4);
        __half2 o[8];
#pragma unroll
        for (int tg = 0; tg < 4; tg++)
#pragma unroll
            for (int rg = 0; rg < 2; rg++)
                o[tg * 2 + rg] = __floats2half2_rn(f[rg * 8 + 2 * tg], f[rg * 8 + 2 * tg + 1]);
        __half2* d = (__half2*)g_xp + (size_t)blk * 4096 + kt * 256 + k16 * 64 + grp * 8;
        *(uint4*)d = *(uint4*)o;
        *(uint4*)(d + 4) = *(uint4*)(o + 4);
    } else if (idx < N1 + N2 + N3) {
        ((uint32_t*)g_hp)[idx - N1 - N2] = 0u;     // zero hp[0]
    } else if (idx < N1 + N2 + N3 + 4) {
        g_sync4[idx - N1 - N2 - N3] = 0u;
    } else if (idx < N1 + N2 + N3 + 4 + 128) {
        g_xdone[idx - N1 - N2 - N3 - 4] = 0u;
    }
}

// ------------------------------ pipeline pieces (BK128, 2 stages) -------------
// Stage: A (weights 128 gate-rows x 128k) 32KB @ +0, B (64 batch x 128k) 16KB @ +32768.
// A issue: 16 chunks/thread; B issue: 8 chunks/thread (128 threads).
#define ISSUE_A(s, KT) do {                                                       \
    uint32_t _d = sb + (uint32_t)(s) * STG_B;                                     \
    const char* _a = Abase + (size_t)(KT) * 32768;                                \
    _Pragma("unroll")                                                             \
    for (int _r = 0; _r < 16; _r++) {                                             \
        int _id = tid + _r * 128;                                                 \
        CP16(_d + _id * 16, _a + _id * 16);                                       \
    }                                                                             \
} while (0)

#define ISSUE_B(s, segbase, K) do {                                               \
    uint32_t _d = sb + (uint32_t)(s) * STG_B + 32768u;                            \
    const char* _b = (segbase) + (size_t)(K) * 2048;                              \
    _Pragma("unroll")                                                             \
    for (int _r = 0; _r < 8; _r++) {                                              \
        int _c = tid + _r * 128;                                                  \
        CP16(_d + _c * 16,                                                        \
             _b + (size_t)(_c >> 7) * 16384 + (size_t)(_c & 127) * 16);           \
    }                                                                             \
} while (0)

// A: [sub(2):16384][wm:8192][mi:2048][k16:512][grp:64][tig:16]
// B: [blk(8):2048][sub(2):1024][k16:256][grp:32][tig:8]; warp wn covers blks wn*4+nj
#define COMPUTE_STAGE(s) do {                                                     \
    uint32_t _aB = sb + (uint32_t)(s) * STG_B + wm * 8192u + grp * 64u + tig * 16u; \
    uint32_t _bB = sb + (uint32_t)(s) * STG_B + 32768u + wn * 8192u + grp * 32u + tig * 8u; \
    uint4 _af[2][4]; uint2 _bf[2][4];                                             \
    _Pragma("unroll")                                                             \
    for (int _mi = 0; _mi < 4; _mi++) _af[0][_mi] = lds128u(_aB + _mi * 2048);    \
    _Pragma("unroll")                                                             \
    for (int _nj = 0; _nj < 4; _nj++) _bf[0][_nj] = lds64u(_bB + _nj * 2048);     \
    _Pragma("unroll")                                                             \
    for (int _k = 0; _k < 8; _k++) {                                              \
        const int _cur = _k & 1, _nxt = _cur ^ 1;                                 \
        if (_k < 7) {                                                             \
            const uint32_t _ao = ((_k + 1) >> 2) * 16384u + ((_k + 1) & 3) * 512u; \
            const uint32_t _bo = ((_k + 1) >> 2) * 1024u  + ((_k + 1) & 3) * 256u; \
            _Pragma("unroll")                                                     \
            for (int _mi = 0; _mi < 4; _mi++)                                     \
                _af[_nxt][_mi] = lds128u(_aB + _ao + _mi * 2048);                 \
            _Pragma("unroll")                                                     \
            for (int _nj = 0; _nj < 4; _nj++)                                     \
                _bf[_nxt][_nj] = lds64u(_bB + _bo + _nj * 2048);                  \
        }                                                                         \
        _Pragma("unroll")                                                         \
        for (int _mi = 0; _mi < 4; _mi++)                                         \
            _Pragma("unroll")                                                     \
            for (int _nj = 0; _nj < 4; _nj++)                                     \
                mma_f16(acc[_mi][_nj], _af[_cur][_mi], _bf[_cur][_nj]);           \
    }                                                                             \
} while (0)

#define ACC_ZERO() do {                                                           \
    _Pragma("unroll")                                                             \
    for (int _a = 0; _a < 4; _a++)                                                \
        _Pragma("unroll")                                                         \
        for (int _b = 0; _b < 4; _b++)                                            \
            _Pragma("unroll")                                                     \
            for (int _c = 0; _c < 4; _c++) acc[_a][_b][_c] = 0.f;                 \
} while (0)

// ------------------------------ persistent X/H LSTM ---------------------------
// grid 256 x 128thr. bids 0..127 = H (consumer: h@R + gates), 128..255 = X
// (producer: zx = x@W, free-running). Tile = 128 gates x 128 batch, processed
// as two 64-batch halves. LUT placement pairs X onto H SMs; X fills H's stalls.
__global__ void __launch_bounds__(128, 2)
lstm_persist(const float* __restrict__ bias, float* __restrict__ out)
{
    extern __shared__ char smem[];
    const uint32_t sb = (uint32_t)__cvta_generic_to_shared(smem);
    const int tid = threadIdx.x, lane = tid & 31, wid = tid >> 5;
    const int wm = wid >> 1, wn = wid & 1;
    const int grp = lane >> 2, tig = lane & 3;
    const int bid = blockIdx.x;
    const bool isH = (bid < 128);
    const int tile = isH ? bid : (bid - 128);
    const int cb = tile >> 2, by = tile & 3;

    const char* Abase = (const char*)g_WRp + (size_t)cb * 524288;

    if (!isH) {
        // ======================= X: zx producer =============================
        // segments: (t, half) stream of 8 x-ktiles each; B always available.
        const char* bseg = (const char*)g_xp + (size_t)(by * 16) * 16384;  // t=0,h=0
        ISSUE_A(0, 0);
        ISSUE_B(0, bseg, 0);
        CP_COMMIT();

        for (int t = 0; t < TSTEPS; t++) {
#pragma unroll 1
            for (int h = 0; h < 2; h++) {
                // next segment's B base (x is padded at t=99,h=1)
                const char* bnext = (const char*)g_xp +
                    (size_t)((h == 0) ? (t * 64 + by * 16 + 8)
                                      : ((t + 1) * 64 + by * 16)) * 16384;
                float acc[4][4][4];
                ACC_ZERO();
                for (int kt = 0; kt < 8; kt++) {
                    __syncthreads();
                    const int la = kt + 1;
                    if (la < 8) {
                        ISSUE_A(la & 1, la);
                        ISSUE_B(la & 1, bseg, la);
                    } else {
                        ISSUE_A(0, 0);
                        ISSUE_B(0, bnext, 0);
                    }
                    CP_COMMIT();
                    CP_WAIT1();
                    __syncthreads();
                    COMPUTE_STAGE(kt & 1);
                }
                bseg = bnext;

                // quantize + store zx half (fragment-linear, 128B/thread)
                const float* pa = &acc[0][0][0];
                uint32_t pk[32];
#pragma unroll
                for (int i = 0; i < 32; i++) pk[i] = packh2(pa[2 * i], pa[2 * i + 1]);
                char* dst = (char*)g_zxh +
                    (((size_t)(t * 128 + tile) * 2 + h) * 16384) + (size_t)tid * 128;
#pragma unroll
                for (int q = 0; q < 8; q++)
                    stg_cg128(dst + q * 16, *(uint4*)(pk + q * 4));
                __threadfence();
                __syncthreads();
                if (tid == 0) atomicAdd(&g_xdone[tile], 1u);
            }
        }
        CP_WAIT0();
    } else {
        // ======================= H: recurrence ==============================
        const int j0 = cb * 32 + wm * 16;
        float bia[2][4];
#pragma unroll
        for (int jhi = 0; jhi < 2; jhi++) {
            const int j = j0 + jhi * 8 + grp;
            bia[jhi][0] = __ldg(bias + j);
            bia[jhi][1] = __ldg(bias + 1024 + j);
            bia[jhi][2] = __ldg(bias + 2048 + j);
            bia[jhi][3] = __ldg(bias + 3072 + j);
        }
        float cr[2][2][4][2];   // [half][jhi][nj][e]
#pragma unroll
        for (int a = 0; a < 2; a++)
#pragma unroll
            for (int b = 0; b < 2; b++)
#pragma unroll
                for (int c = 0; c < 4; c++) { cr[a][b][c][0] = 0.f; cr[a][b][c][1] = 0.f; }

        ISSUE_A(0, 8);   // R ktile 8 prefetch
        CP_COMMIT();

        for (int t = 0; t < TSTEPS; t++) {
            if (t > 0) {
                const unsigned tgt = (unsigned)t * 32u;
                while (*(volatile unsigned*)&g_sync4[by] < tgt) { }
                __threadfence();
            }
            __half* hw = g_hp[(t & 1) ^ 1];

#pragma unroll 1
            for (int h = 0; h < 2; h++) {
                const char* bseg = (const char*)g_hp[t & 1] +
                    (size_t)(by * 16 + h * 8) * 16384;
                ISSUE_B(0, bseg, 0);
                CP_COMMIT();

                float acc[4][4][4];
                ACC_ZERO();
                for (int kt = 0; kt < 8; kt++) {
                    __syncthreads();
                    const int la = kt + 1;
                    if (la < 8) {
                        ISSUE_A(la & 1, 8 + la);
                        ISSUE_B(la & 1, bseg, la);
                    } else {
                        ISSUE_A(0, 8);   // next segment's first A (R K8)
                    }
                    CP_COMMIT();
                    CP_WAIT1();
                    __syncthreads();
                    COMPUTE_STAGE(kt & 1);
                }

                // wait for zx(t, h), add it
                {
                    const unsigned tgt = (unsigned)(t * 2 + h + 1);
                    while (*(volatile unsigned*)&g_xdone[tile] < tgt) { }
                    __threadfence();
                }
                float* pa = &acc[0][0][0];
                const char* zsrc = (const char*)g_zxh +
                    (((size_t)(t * 128 + tile) * 2 + h) * 16384) + (size_t)tid * 128;
#pragma unroll
                for (int q = 0; q < 8; q++) {
                    uint4 v = ldg_cg128(zsrc + q * 16);
                    float2 f0 = __half22float2(*(__half2*)&v.x);
                    float2 f1 = __half22float2(*(__half2*)&v.y);
                    float2 f2 = __half22float2(*(__half2*)&v.z);
                    float2 f3 = __half22float2(*(__half2*)&v.w);
                    pa[q * 8 + 0] += f0.x; pa[q * 8 + 1] += f0.y;
                    pa[q * 8 + 2] += f1.x; pa[q * 8 + 3] += f1.y;
                    pa[q * 8 + 4] += f2.x; pa[q * 8 + 5] += f2.y;
                    pa[q * 8 + 6] += f3.x; pa[q * 8 + 7] += f3.y;
                }

                // gates + state update for this half
                float hnv[2][4][2];
#pragma unroll
                for (int jhi = 0; jhi < 2; jhi++) {
                    const int j = j0 + jhi * 8 + grp;
                    const int kt_  = j >> 6;
                    const int k16_ = (j >> 4) & 3;
                    const int reg_ = (j >> 3) & 1;
                    const int tig_ = (j >> 1) & 3;
                    const int u_   = j & 1;
                    const int jbase = (kt_ * 4 + k16_) * 32;
#pragma unroll
                    for (int nj = 0; nj < 4; nj++) {
                        const int blk = by * 16 + h * 8 + wn * 4 + nj;
#pragma unroll
                        for (int e = 0; e < 2; e++) {
                            const int grp_b = tig * 2 + e;
                            float zi = acc[2 * jhi    ][nj][e]     + bia[jhi][0];
                            float zf = acc[2 * jhi    ][nj][2 + e] + bia[jhi][1];
                            float zg = acc[2 * jhi + 1][nj][e]     + bia[jhi][2];
                            float zo = acc[2 * jhi + 1][nj][2 + e] + bia[jhi][3];
                            float si = sigm_f(zi), sf = sigm_f(zf), so = sigm_f(zo);
                            float tg = tanh_f(zg);
                            float cn = sf * cr[h][jhi][nj][e] + si * tg;
                            float hn = so * tanh_f(cn);
                            cr[h][jhi][nj][e] = cn;
                            hnv[jhi][nj][e] = hn;
                            hw[(size_t)blk * 8192 + (jbase + grp_b * 4 + tig_) * 4
                               + reg_ * 2 + u_] = __float2half_rn(hn);
                        }
                    }
                }

                if (h == 1) {   // both halves written -> publish h(t+1)
                    __threadfence();
                    __syncthreads();
                    if (tid == 0) atomicAdd(&g_sync4[by], 1u);
                }

                // out stores (not on the h critical path)
#pragma unroll
                for (int jhi = 0; jhi < 2; jhi++) {
                    const int j = j0 + jhi * 8 + grp;
#pragma unroll
                    for (int nj = 0; nj < 4; nj++) {
                        const int blk = by * 16 + h * 8 + wn * 4 + nj;
#pragma unroll
                        for (int e = 0; e < 2; e++) {
                            const int b = blk * 8 + tig * 2 + e;
                            out[(size_t)b * (TSTEPS * HIDDEN) + (size_t)t * 1024 + j]
                                = hnv[jhi][nj][e];
                        }
                    }
                }
            }
        }
        CP_WAIT0();
    }
}

// ------------------------------ launch ----------------------------------------
extern "C" void kernel_launch(void* const* d_in, const int* in_sizes, int n_in,
                              void* d_out, int out_size)
{
    const float* x    = (const float*)d_in[0];  // [512, 103, 1024]
    const float* W    = (const float*)d_in[1];  // [1024, 4096]
    const float* R    = (const float*)d_in[2];  // [1024, 4096]
    const float* bias = (const float*)d_in[3];  // [4096]
    float* out = (float*)d_out;                 // [512, 100, 1024]

    cudaFuncSetAttribute(lstm_persist, cudaFuncAttributeMaxDynamicSharedMemorySize, SMEM_SZ);
    cudaFuncSetAttribute(lstm_persist, cudaFuncAttributePreferredSharedMemoryCarveout, 100);

    const int total = N1 + N2 + N3 + 4 + 128;
    prep_all<<<(total + 255) / 256, 256>>>(W, R, x);

    // H = bids 0..127 (one per SM first), X = bids 128..255 (pair onto H SMs)
    lstm_persist<<<256, 128, SMEM_SZ>>>(bias, out);
}

// round 17
// speedup vs baseline: 1.1599x; 1.1599x over previous
#include <cuda_runtime.h>
#include <cuda_fp16.h>
#include <cstdint>
#include <math.h>

#define HIDDEN   1024
#define BATCH    512
#define FEAT     1024
#define TSTEPS   100
#define TIME_TOT 103
#define FOURH    4096
#define MTOT     (TSTEPS * BATCH)   // 51200

// 3 stages x (A 32KB + B 32KB) = 192KB, 1 CTA/SM
#define STG_B    65536
#define SMEM_SZ  196608

// ------------------------------ scratch (device globals, no allocs) ----------
__device__ __align__(16) __half g_WRp[32 * 32 * 8192];         // [W;R] fp16 per-strip (16MB)
__device__ __align__(16) __half g_xp[(size_t)MTOT * 1024];     // permuted x fp16 (100MB)
__device__ __align__(16) __half g_hp[2][BATCH * HIDDEN];       // permuted h fp16 ping-pong
__device__ unsigned g_sync4[4];                                // per-by counters (32 CTAs each)

// ------------------------------ asm helpers ----------------------------------
#define CP16(dst, src) \
    asm volatile("cp.async.cg.shared.global [%0], [%1], 16;" :: "r"(dst), "l"(src))
#define CP_COMMIT() asm volatile("cp.async.commit_group;" ::: "memory")
#define CP_WAIT1()  asm volatile("cp.async.wait_group 1;" ::: "memory")

__device__ __forceinline__ uint4 lds128u(uint32_t a) {
    uint4 v;
    asm volatile("ld.shared.v4.b32 {%0,%1,%2,%3}, [%4];"
                 : "=r"(v.x), "=r"(v.y), "=r"(v.z), "=r"(v.w) : "r"(a));
    return v;
}
__device__ __forceinline__ uint2 lds64u(uint32_t a) {
    uint2 v;
    asm volatile("ld.shared.v2.b32 {%0,%1}, [%2];" : "=r"(v.x), "=r"(v.y) : "r"(a));
    return v;
}
__device__ __forceinline__ void mma_f16(float c[4], uint4 a, uint2 b) {
    asm volatile(
        "mma.sync.aligned.m16n8k16.row.col.f32.f16.f16.f32 "
        "{%0,%1,%2,%3}, {%4,%5,%6,%7}, {%8,%9}, {%0,%1,%2,%3};"
        : "+f"(c[0]), "+f"(c[1]), "+f"(c[2]), "+f"(c[3])
        : "r"(a.x), "r"(a.y), "r"(a.z), "r"(a.w), "r"(b.x), "r"(b.y));
}
__device__ __forceinline__ float sigm_f(float z) {
    return __fdividef(1.f, 1.f + __expf(-z));
}
__device__ __forceinline__ float tanh_f(float z) {
    return 1.f - __fdividef(2.f, __expf(2.f * z) + 1.f);
}

// ------------------------------ prep (single launch) --------------------------
#define N1 (32 * 32 * 4096)          // WRp half2 elems
#define N2 (MTOT * 1024 / 16)        // xp 16-float chunks
#define N3 (BATCH * HIDDEN / 2)      // hp[0] zero words

__global__ void prep_all(const float* __restrict__ W, const float* __restrict__ R,
                         const float* __restrict__ x)
{
    int idx = blockIdx.x * blockDim.x + threadIdx.x;
    if (idx < N1) {
        int v   = idx & 3;
        int tig = (idx >> 2) & 3;
        int grp = (idx >> 4) & 7;
        int k16 = (idx >> 7) & 3;
        int mi  = (idx >> 9) & 3;
        int wm  = (idx >> 11) & 1;
        int kt  = (idx >> 12) & 31;
        int cb  = idx >> 17;
        int r8  = v & 1;
        int khi = (v >> 1) * 8;
        int q   = mi * 2 + r8;
        int gate = q & 3;
        int jhi  = q >> 2;
        int j = cb * 32 + wm * 16 + jhi * 8 + grp;
        int kl = k16 * 16 + khi + 2 * tig;
        const float* src = (kt < 16) ? W : R;
        int k = (kt < 16 ? kt : kt - 16) * 64 + kl;
        int col = gate * 1024 + j;
        ((__half2*)g_WRp)[idx] = __floats2half2_rn(src[(size_t)k * FOURH + col],
                                                   src[(size_t)(k + 1) * FOURH + col]);
    } else if (idx < N1 + N2) {
        int id = idx - N1;
        int grp = id & 7;
        int k16 = (id >> 3) & 3;
        int kt  = (id >> 5) & 15;
        int blk = id >> 9;
        int m = blk * 8 + grp;
        int t = m >> 9, bb = m & 511;
        const float* s = x + ((size_t)bb * TIME_TOT + t) * FEAT + kt * 64 + k16 * 16;
        float f[16];
#pragma unroll
        for (int qd = 0; qd < 4; qd++) *(float4*)(f + qd * 4) = *(const float4*)(s + qd * 4);
        __half2 o[8];
#pragma unroll
        for (int tg = 0; tg < 4; tg++)
#pragma unroll
            for (int rg = 0; rg < 2; rg++)
                o[tg * 2 + rg] = __floats2half2_rn(f[rg * 8 + 2 * tg], f[rg * 8 + 2 * tg + 1]);
        __half2* d = (__half2*)g_xp + (size_t)blk * 4096 + kt * 256 + k16 * 64 + grp * 8;
        *(uint4*)d = *(uint4*)o;
        *(uint4*)(d + 4) = *(uint4*)(o + 4);
    } else if (idx < N1 + N2 + N3) {
        ((uint32_t*)g_hp)[idx - N1 - N2] = 0u;     // zero hp[0]
    } else if (idx < N1 + N2 + N3 + 4) {
        g_sync4[idx - N1 - N2 - N3] = 0u;
    }
}

// ------------------------------ pipeline pieces (BK128, 3 stages) -------------
// Stage: A (weights, 128 gate-rows) 32KB @ +0, B (128 batch) 32KB @ +32768.
// 128 threads: A 16 chunks/thread, B 16 chunks/thread.
#define ISSUE_STAGE(s, K, bxp, bhp) do {                                          \
    uint32_t _stA = sb + (uint32_t)(s) * STG_B;                                   \
    uint32_t _stB = _stA + 32768u;                                                \
    const char* _as = Abase + (size_t)(K) * 32768;                                \
    _Pragma("unroll")                                                             \
    for (int _r = 0; _r < 16; _r++) {                                             \
        int _id = tid + _r * 128;                                                 \
        CP16(_stA + _id * 16, _as + _id * 16);                                    \
    }                                                                             \
    const char* _bsrc = ((K) < 8) ? ((bxp) + (size_t)(K) * 2048)                  \
                                  : ((bhp) + (size_t)((K) - 8) * 2048);           \
    _Pragma("unroll")                                                             \
    for (int _r = 0; _r < 16; _r++) {                                             \
        int _c = tid + _r * 128;                                                  \
        CP16(_stB + _c * 16,                                                      \
             _bsrc + (size_t)(_c >> 7) * 16384 + (size_t)(_c & 127) * 16);        \
    }                                                                             \
} while (0)

// warp tile 64x64: wm in {0,1} (A rows), wn in {0,1} (B: 8 blks each).
// A: [sub(2):16384][wm:8192][mi:2048][k16:512][grp:64][tig:16]
// B: [blk(16):2048][sub(2):1024][k16:256][grp:32][tig:8]
#define COMPUTE_STAGE(s) do {                                                     \
    uint32_t _aB = sb + (uint32_t)(s) * STG_B + wm * 8192u + grp * 64u + tig * 16u; \
    uint32_t _bB = sb + (uint32_t)(s) * STG_B + 32768u + wn * 16384u + grp * 32u + tig * 8u; \
    _Pragma("unroll")                                                             \
    for (int _k = 0; _k < 8; _k++) {                                              \
        const uint32_t _ao = (_k >> 2) * 16384u + (_k & 3) * 512u;                \
        const uint32_t _bo = (_k >> 2) * 1024u  + (_k & 3) * 256u;                \
        uint4 _af[4]; uint2 _bf[8];                                               \
        _Pragma("unroll")                                                         \
        for (int _mi = 0; _mi < 4; _mi++)                                         \
            _af[_mi] = lds128u(_aB + _ao + _mi * 2048u);                          \
        _Pragma("unroll")                                                         \
        for (int _nj = 0; _nj < 8; _nj++)                                         \
            _bf[_nj] = lds64u(_bB + _bo + _nj * 2048u);                           \
        _Pragma("unroll")                                                         \
        for (int _mi = 0; _mi < 4; _mi++)                                         \
            _Pragma("unroll")                                                     \
            for (int _nj = 0; _nj < 8; _nj++)                                     \
                mma_f16(acc[_mi][_nj], _af[_mi], _bf[_nj]);                       \
    }                                                                             \
} while (0)

// ------------------------------ persistent fused LSTM -------------------------
// grid (32,4), 128 thr, 1 CTA/SM. Tile 128(gates) x 128(batch); warp 64x64.
// Byte-optimal: 64B of fragment LDS per MMA (square tile) vs 96B before.
// 3-stage pipeline, single sync/ktile; stage of local kt at step t = (t+kt)%3.
__global__ void __launch_bounds__(128, 1)
lstm_persist(const float* __restrict__ bias, float* __restrict__ out)
{
    extern __shared__ char smem[];
    const uint32_t sb = (uint32_t)__cvta_generic_to_shared(smem);
    const int tid = threadIdx.x, lane = tid & 31, wid = tid >> 5;
    const int wm = wid >> 1, wn = wid & 1;
    const int grp = lane >> 2, tig = lane & 3;
    const int cb = blockIdx.x, by = blockIdx.y;

    const char* Abase = (const char*)g_WRp + (size_t)cb * 524288;
    const size_t bblk0 = (size_t)(by * 16) * 16384;

    const int j0 = cb * 32 + wm * 16;
    float bia[2][4];
#pragma unroll
    for (int jhi = 0; jhi < 2; jhi++) {
        const int j = j0 + jhi * 8 + grp;
        bia[jhi][0] = __ldg(bias + j);
        bia[jhi][1] = __ldg(bias + 1024 + j);
        bia[jhi][2] = __ldg(bias + 2048 + j);
        bia[jhi][3] = __ldg(bias + 3072 + j);
    }
    float cr[2][8][2];
#pragma unroll
    for (int a = 0; a < 2; a++)
#pragma unroll
        for (int b = 0; b < 8; b++) { cr[a][b][0] = 0.f; cr[a][b][1] = 0.f; }

    // prologue: global ktiles 0,1 (t=0) -> stages 0,1
    {
        const char* Bx = (const char*)g_xp + bblk0;
        const char* Bh = (const char*)g_hp[0] + bblk0;
        ISSUE_STAGE(0, 0, Bx, Bh); CP_COMMIT();
        ISSUE_STAGE(1, 1, Bx, Bh); CP_COMMIT();
    }

    for (int t = 0; t < TSTEPS; t++) {
        const char* Bx  = (const char*)g_xp + (size_t)t * 64 * 16384 + bblk0;
        const char* Bh  = (const char*)g_hp[t & 1] + bblk0;
        const char* BxN = Bx + (size_t)64 * 16384;
        __half* hw = g_hp[(t & 1) ^ 1];

        float acc[4][8][4];
#pragma unroll
        for (int a = 0; a < 4; a++)
#pragma unroll
            for (int b = 0; b < 8; b++)
#pragma unroll
                for (int c = 0; c < 4; c++) acc[a][b][c] = 0.f;

        for (int kt = 0; kt < 16; kt++) {
            CP_WAIT1();
            __syncthreads();
            if (kt == 6 && t > 0) {
                // K=8 (first h tile) issues THIS iteration (la = 8)
                const unsigned tgt = (unsigned)t * 32u;
                while (*(volatile unsigned*)&g_sync4[by] < tgt) { }
                __threadfence();
            }
            const int la = kt + 2;
            const int is = (t + la) % 3;           // global-phase stage index
            if (la < 16) {
                ISSUE_STAGE(is, la, Bx, Bh);
            } else if (t + 1 < TSTEPS) {
                ISSUE_STAGE(is, la - 16, BxN, Bh); // next step's x ktiles 0,1
            }
            CP_COMMIT();
            COMPUTE_STAGE((t + kt) % 3);
        }

        // ---- fused LSTM epilogue (c in registers; hn reuses dead acc slots) ----
#pragma unroll
        for (int jhi = 0; jhi < 2; jhi++) {
            const int j = j0 + jhi * 8 + grp;
            const int kt_  = j >> 6;
            const int k16_ = (j >> 4) & 3;
            const int reg_ = (j >> 3) & 1;
            const int tig_ = (j >> 1) & 3;
            const int u_   = j & 1;
            const int jbase = (kt_ * 4 + k16_) * 32;
#pragma unroll
            for (int nj = 0; nj < 8; nj++) {
                const int blk = by * 16 + wn * 8 + nj;
#pragma unroll
                for (int e = 0; e < 2; e++) {
                    const int grp_b = tig * 2 + e;
                    float zi = acc[2 * jhi    ][nj][e]     + bia[jhi][0];
                    float zf = acc[2 * jhi    ][nj][2 + e] + bia[jhi][1];
                    float zg = acc[2 * jhi + 1][nj][e]     + bia[jhi][2];
                    float zo = acc[2 * jhi + 1][nj][2 + e] + bia[jhi][3];

                    float si = sigm_f(zi);
                    float sf = sigm_f(zf);
                    float so = sigm_f(zo);
                    float tg = tanh_f(zg);

                    float cn = sf * cr[jhi][nj][e] + si * tg;
                    float hn = so * tanh_f(cn);
                    cr[jhi][nj][e] = cn;
                    acc[2 * jhi][nj][e] = hn;     // stash hn in dead acc slot
                    hw[(size_t)blk * 8192 + (jbase + grp_b * 4 + tig_) * 4 + reg_ * 2 + u_] =
                        __float2half_rn(hn);
                }
            }
        }

        // publish h, arrive, then out stores (off the h critical path)
        __syncthreads();
        if (tid == 0) {
            __threadfence();
            atomicAdd(&g_sync4[by], 1u);
        }

#pragma unroll
        for (int jhi = 0; jhi < 2; jhi++) {
            const int j = j0 + jhi * 8 + grp;
#pragma unroll
            for (int nj = 0; nj < 8; nj++) {
                const int blk = by * 16 + wn * 8 + nj;
#pragma unroll
                for (int e = 0; e < 2; e++) {
                    const int b = blk * 8 + tig * 2 + e;
                    out[(size_t)b * (TSTEPS * HIDDEN) + (size_t)t * 1024 + j]
                        = acc[2 * jhi][nj][e];
                }
            }
        }
    }
}

// ------------------------------ launch ----------------------------------------
extern "C" void kernel_launch(void* const* d_in, const int* in_sizes, int n_in,
                              void* d_out, int out_size)
{
    const float* x    = (const float*)d_in[0];  // [512, 103, 1024]
    const float* W    = (const float*)d_in[1];  // [1024, 4096]
    const float* R    = (const float*)d_in[2];  // [1024, 4096]
    const float* bias = (const float*)d_in[3];  // [4096]
    float* out = (float*)d_out;                 // [512, 100, 1024]

    cudaFuncSetAttribute(lstm_persist, cudaFuncAttributeMaxDynamicSharedMemorySize, SMEM_SZ);

    const int total = N1 + N2 + N3 + 4;
    prep_all<<<(total + 255) / 256, 256>>>(W, R, x);

    dim3 grid(32, 4);   // 128 CTAs, 1/SM, co-resident
    lstm_persist<<<grid, 128, SMEM_SZ>>>(bias, out);
}